// round 6
// baseline (speedup 1.0000x reference)
#include <cuda_runtime.h>
#include <math.h>

// ---------------- problem constants ----------------
#define NSEQ 256
#define LRES 384
#define DM   256
#define DP   128
#define NH   8
#define DH   32
#define MROWS (NSEQ*LRES)       // 98304
#define PROWS (LRES*LRES)       // 147456
#define SCALE 0.17677669529663687f  // 1/sqrt(32)

// ---------------- scratch (static device globals; no allocation) ----------------
__device__ float g_msa_n[MROWS*DM];
__device__ float g_q    [MROWS*DM];
__device__ float g_k    [MROWS*DM];
__device__ float g_v    [MROWS*DM];
__device__ float g_gate [MROWS*DM];
__device__ float g_swk  [MROWS*DM];
__device__ float g_outp [MROWS*DM];
__device__ float g_swq  [LRES*DM];
__device__ float g_bias [NH*PROWS];
__device__ float g_attn [NH*PROWS];

// ---------------- 1) LayerNorm over msa (D=256) ----------------
__global__ __launch_bounds__(256) void ln_msa_kernel(
    const float* __restrict__ msa, const float* __restrict__ g, const float* __restrict__ b)
{
    int row = blockIdx.x;
    int t   = threadIdx.x;
    float x = msa[row*DM + t];
    float s = x, s2 = x*x;
    #pragma unroll
    for (int o = 16; o > 0; o >>= 1) {
        s  += __shfl_xor_sync(0xffffffffu, s,  o);
        s2 += __shfl_xor_sync(0xffffffffu, s2, o);
    }
    __shared__ float ws[8], ws2[8];
    int w = t >> 5;
    if ((t & 31) == 0) { ws[w] = s; ws2[w] = s2; }
    __syncthreads();
    float tot = 0.f, tot2 = 0.f;
    #pragma unroll
    for (int i = 0; i < 8; i++) { tot += ws[i]; tot2 += ws2[i]; }
    float mean = tot * (1.0f/DM);
    float var  = tot2 * (1.0f/DM) - mean*mean;
    float rs   = rsqrtf(var + 1e-5f);
    g_msa_n[row*DM + t] = (x - mean) * rs * g[t] + b[t];
}

// ---------------- 2) pair LayerNorm fused with bias = pair_n @ wb ----------------
// one block per pair row r = q*384+k; 128 threads; writes g_bias[h][q][k]
__global__ __launch_bounds__(128) void pair_bias_kernel(
    const float* __restrict__ pair, const float* __restrict__ g, const float* __restrict__ b,
    const float* __restrict__ wb)
{
    int r = blockIdx.x;
    int t = threadIdx.x;
    float x = pair[r*DP + t];
    float s = x, s2 = x*x;
    #pragma unroll
    for (int o = 16; o > 0; o >>= 1) {
        s  += __shfl_xor_sync(0xffffffffu, s,  o);
        s2 += __shfl_xor_sync(0xffffffffu, s2, o);
    }
    __shared__ float ws[4], ws2[4];
    int w = t >> 5;
    if ((t & 31) == 0) { ws[w] = s; ws2[w] = s2; }
    __syncthreads();
    float tot = ws[0]+ws[1]+ws[2]+ws[3];
    float tot2 = ws2[0]+ws2[1]+ws2[2]+ws2[3];
    float mean = tot * (1.0f/DP);
    float var  = tot2 * (1.0f/DP) - mean*mean;
    float rs   = rsqrtf(var + 1e-5f);
    float xn   = (x - mean) * rs * g[t] + b[t];

    float acc[NH];
    #pragma unroll
    for (int h = 0; h < NH; h++) acc[h] = xn * wb[t*NH + h];
    #pragma unroll
    for (int o = 16; o > 0; o >>= 1) {
        #pragma unroll
        for (int h = 0; h < NH; h++) acc[h] += __shfl_xor_sync(0xffffffffu, acc[h], o);
    }
    __shared__ float part[4][NH];
    if ((t & 31) == 0) {
        #pragma unroll
        for (int h = 0; h < NH; h++) part[w][h] = acc[h];
    }
    __syncthreads();
    if (t < NH) {
        float v = part[0][t] + part[1][t] + part[2][t] + part[3][t];
        g_bias[t*PROWS + r] = v;
    }
}

// ---------------- 3) swq = (tar @ sw_q_w + b) * scale ; tar = msa_n row l (n=0) ----------------
__global__ __launch_bounds__(256) void swq_kernel(
    const float* __restrict__ sw_q_w, const float* __restrict__ sw_q_b)
{
    int l = blockIdx.x;
    int j = threadIdx.x;
    __shared__ float tarr[DM];
    tarr[j] = g_msa_n[l*DM + j];
    __syncthreads();
    float acc = sw_q_b[j];
    #pragma unroll 8
    for (int d = 0; d < DM; d++) acc += tarr[d] * sw_q_w[d*DM + j];
    g_swq[l*DM + j] = acc * SCALE;
}

// ---------------- 4) tiled SGEMM: C(98304x256) = A(98304x256) @ W(256x256), fused epilogue ----------------
// mode: 0 swk(+bias), 1 q, 2 k(*scale), 3 v, 4 gate(sigmoid+bias), 5 final(+bias -> out_ext)
__global__ __launch_bounds__(256) void sgemm256(
    const float* __restrict__ W, const float* __restrict__ bias, float* out_ext, int mode)
{
    const float* A = (mode == 5) ? g_outp : g_msa_n;
    float* C;
    switch (mode) {
        case 0: C = g_swk;  break;
        case 1: C = g_q;    break;
        case 2: C = g_k;    break;
        case 3: C = g_v;    break;
        case 4: C = g_gate; break;
        default: C = out_ext; break;
    }
    __shared__ float As[32][68];   // [k][m], padded
    __shared__ float Bs[32][64];   // [k][n]
    int m0 = blockIdx.x * 64, n0 = blockIdx.y * 64;
    int tid = threadIdx.x;
    int tx = tid & 15, ty = tid >> 4;
    float acc[4][4] = {};

    for (int kk = 0; kk < DM; kk += 32) {
        #pragma unroll
        for (int i = 0; i < 2; i++) {
            int id = tid + i*256;
            int r = id >> 3, c4 = (id & 7) * 4;
            float4 v = *(const float4*)&A[(m0 + r)*DM + kk + c4];
            As[c4+0][r] = v.x; As[c4+1][r] = v.y; As[c4+2][r] = v.z; As[c4+3][r] = v.w;
        }
        #pragma unroll
        for (int i = 0; i < 2; i++) {
            int id = tid + i*256;
            int r = id >> 4, c4 = (id & 15) * 4;
            *(float4*)&Bs[r][c4] = *(const float4*)&W[(kk + r)*DM + n0 + c4];
        }
        __syncthreads();
        #pragma unroll
        for (int k = 0; k < 32; k++) {
            float a[4], b[4];
            *(float4*)a = *(const float4*)&As[k][ty*4];
            *(float4*)b = *(const float4*)&Bs[k][tx*4];
            #pragma unroll
            for (int i = 0; i < 4; i++)
                #pragma unroll
                for (int j = 0; j < 4; j++)
                    acc[i][j] += a[i] * b[j];
        }
        __syncthreads();
    }

    #pragma unroll
    for (int i = 0; i < 4; i++) {
        int m = m0 + ty*4 + i;
        float4 o;
        float c[4];
        #pragma unroll
        for (int j = 0; j < 4; j++) {
            int n = n0 + tx*4 + j;
            float v = acc[i][j];
            if      (mode == 0) v += bias[n];
            else if (mode == 2) v *= SCALE;
            else if (mode == 4) v = 1.f / (1.f + __expf(-(v + bias[n])));
            else if (mode == 5) v += bias[n];
            c[j] = v;
        }
        o.x = c[0]; o.y = c[1]; o.z = c[2]; o.w = c[3];
        *(float4*)&C[m*DM + n0 + tx*4] = o;
    }
}

// ---------------- 5) seq-weight: logits over n, softmax over n, scale q in place ----------------
// grid (LRES, NH), 256 threads (one per n)
__global__ __launch_bounds__(256) void seqw_kernel()
{
    int l = blockIdx.x, h = blockIdx.y;
    int n = threadIdx.x;
    __shared__ float qv[DH];
    __shared__ float red[8];
    if (n < DH) qv[n] = g_swq[l*DM + h*DH + n];
    __syncthreads();

    const float* kp = &g_swk[(n*LRES + l)*DM + h*DH];
    float dot = 0.f;
    #pragma unroll
    for (int d = 0; d < DH; d += 4) {
        float4 kv = *(const float4*)&kp[d];
        dot += qv[d]*kv.x + qv[d+1]*kv.y + qv[d+2]*kv.z + qv[d+3]*kv.w;
    }
    // softmax over the 256 n values
    float m = dot;
    #pragma unroll
    for (int o = 16; o > 0; o >>= 1) m = fmaxf(m, __shfl_xor_sync(0xffffffffu, m, o));
    int w = n >> 5;
    if ((n & 31) == 0) red[w] = m;
    __syncthreads();
    float mx = red[0];
    #pragma unroll
    for (int i = 1; i < 8; i++) mx = fmaxf(mx, red[i]);
    __syncthreads();
    float e = __expf(dot - mx);
    float s = e;
    #pragma unroll
    for (int o = 16; o > 0; o >>= 1) s += __shfl_xor_sync(0xffffffffu, s, o);
    if ((n & 31) == 0) red[w] = s;
    __syncthreads();
    float tot = 0.f;
    #pragma unroll
    for (int i = 0; i < 8; i++) tot += red[i];
    float wgt = e / tot;

    float* qp = &g_q[(n*LRES + l)*DM + h*DH];
    #pragma unroll
    for (int d = 0; d < DH; d += 4) {
        float4 v = *(float4*)&qp[d];
        v.x *= wgt; v.y *= wgt; v.z *= wgt; v.w *= wgt;
        *(float4*)&qp[d] = v;
    }
}

// ---------------- 6) attn logits: A_h[q,k] = sum_{s,d} q[s,q,h,d]*k[s,k,h,d] ----------------
// grid (6,6,8): 64x64 tile per block
__global__ __launch_bounds__(256) void attn_gemm_kernel()
{
    int h  = blockIdx.z;
    int q0 = blockIdx.x * 64, k0 = blockIdx.y * 64;
    __shared__ float Qs[64][33];
    __shared__ float Ks[64][33];
    int tid = threadIdx.x;
    int tx = tid & 15, ty = tid >> 4;
    float acc[4][4] = {};

    for (int s = 0; s < NSEQ; s++) {
        #pragma unroll
        for (int i = 0; i < 2; i++) {
            int id = tid + i*256;
            int r = id >> 3, c4 = (id & 7) * 4;
            float4 v = *(const float4*)&g_q[(s*LRES + q0 + r)*DM + h*DH + c4];
            Qs[r][c4+0] = v.x; Qs[r][c4+1] = v.y; Qs[r][c4+2] = v.z; Qs[r][c4+3] = v.w;
            float4 u = *(const float4*)&g_k[(s*LRES + k0 + r)*DM + h*DH + c4];
            Ks[r][c4+0] = u.x; Ks[r][c4+1] = u.y; Ks[r][c4+2] = u.z; Ks[r][c4+3] = u.w;
        }
        __syncthreads();
        #pragma unroll
        for (int d = 0; d < 32; d++) {
            float a0 = Qs[ty*4+0][d], a1 = Qs[ty*4+1][d], a2 = Qs[ty*4+2][d], a3 = Qs[ty*4+3][d];
            float b0 = Ks[tx*4+0][d], b1 = Ks[tx*4+1][d], b2 = Ks[tx*4+2][d], b3 = Ks[tx*4+3][d];
            acc[0][0] += a0*b0; acc[0][1] += a0*b1; acc[0][2] += a0*b2; acc[0][3] += a0*b3;
            acc[1][0] += a1*b0; acc[1][1] += a1*b1; acc[1][2] += a1*b2; acc[1][3] += a1*b3;
            acc[2][0] += a2*b0; acc[2][1] += a2*b1; acc[2][2] += a2*b2; acc[2][3] += a2*b3;
            acc[3][0] += a3*b0; acc[3][1] += a3*b1; acc[3][2] += a3*b2; acc[3][3] += a3*b3;
        }
        __syncthreads();
    }
    #pragma unroll
    for (int i = 0; i < 4; i++)
        #pragma unroll
        for (int j = 0; j < 4; j++)
            g_attn[h*PROWS + (q0 + ty*4 + i)*LRES + (k0 + tx*4 + j)] = acc[i][j];
}

// ---------------- 7) softmax over k of (logits + bias) ----------------
// grid (LRES, NH): one block per (q,h); 128 threads, 3 values each
__global__ __launch_bounds__(128) void attn_softmax_kernel()
{
    int q = blockIdx.x, h = blockIdx.y;
    int t = threadIdx.x;
    int base = h*PROWS + q*LRES;
    float v0 = g_attn[base + t      ] + g_bias[base + t      ];
    float v1 = g_attn[base + t + 128] + g_bias[base + t + 128];
    float v2 = g_attn[base + t + 256] + g_bias[base + t + 256];
    float m = fmaxf(v0, fmaxf(v1, v2));
    #pragma unroll
    for (int o = 16; o > 0; o >>= 1) m = fmaxf(m, __shfl_xor_sync(0xffffffffu, m, o));
    __shared__ float red[4];
    int w = t >> 5;
    if ((t & 31) == 0) red[w] = m;
    __syncthreads();
    float mx = fmaxf(fmaxf(red[0], red[1]), fmaxf(red[2], red[3]));
    __syncthreads();
    float e0 = __expf(v0 - mx), e1 = __expf(v1 - mx), e2 = __expf(v2 - mx);
    float s = e0 + e1 + e2;
    #pragma unroll
    for (int o = 16; o > 0; o >>= 1) s += __shfl_xor_sync(0xffffffffu, s, o);
    if ((t & 31) == 0) red[w] = s;
    __syncthreads();
    float tot = red[0] + red[1] + red[2] + red[3];
    float inv = 1.f / tot;
    g_attn[base + t      ] = e0 * inv;
    g_attn[base + t + 128] = e1 * inv;
    g_attn[base + t + 256] = e2 * inv;
}

// ---------------- 8) out[s,q,h,:] = sum_k attn[h,q,k]*v[s,k,h,:] ; * gate ----------------
// grid (6, NSEQ, NH); block 64(q) x 32(d) tile
__global__ __launch_bounds__(256) void out_gemm_kernel()
{
    int q0 = blockIdx.x * 64;
    int s  = blockIdx.y;
    int h  = blockIdx.z;
    __shared__ float As[64][33];   // attn [q][k-chunk]
    __shared__ float Bs[32][33];   // v    [k][d]
    int tid = threadIdx.x;
    int tx = tid & 15, ty = tid >> 4;
    float acc[4][2] = {};

    for (int k0 = 0; k0 < LRES; k0 += 32) {
        #pragma unroll
        for (int i = 0; i < 2; i++) {
            int id = tid + i*256;
            int r = id >> 3, c4 = (id & 7) * 4;
            float4 v = *(const float4*)&g_attn[h*PROWS + (q0 + r)*LRES + k0 + c4];
            As[r][c4+0] = v.x; As[r][c4+1] = v.y; As[r][c4+2] = v.z; As[r][c4+3] = v.w;
        }
        {
            int r = tid >> 3, c4 = (tid & 7) * 4;
            float4 v = *(const float4*)&g_v[(s*LRES + k0 + r)*DM + h*DH + c4];
            Bs[r][c4+0] = v.x; Bs[r][c4+1] = v.y; Bs[r][c4+2] = v.z; Bs[r][c4+3] = v.w;
        }
        __syncthreads();
        #pragma unroll
        for (int kk = 0; kk < 32; kk++) {
            float b0 = Bs[kk][tx*2], b1 = Bs[kk][tx*2+1];
            #pragma unroll
            for (int i = 0; i < 4; i++) {
                float a = As[ty*4+i][kk];
                acc[i][0] += a * b0;
                acc[i][1] += a * b1;
            }
        }
        __syncthreads();
    }
    #pragma unroll
    for (int i = 0; i < 4; i++) {
        int q = q0 + ty*4 + i;
        int idx = (s*LRES + q)*DM + h*DH + tx*2;
        g_outp[idx  ] = acc[i][0] * g_gate[idx  ];
        g_outp[idx+1] = acc[i][1] * g_gate[idx+1];
    }
}

// ---------------- launch ----------------
extern "C" void kernel_launch(void* const* d_in, const int* in_sizes, int n_in,
                              void* d_out, int out_size)
{
    (void)in_sizes; (void)n_in; (void)out_size;
    const float* msa       = (const float*)d_in[0];
    const float* pair      = (const float*)d_in[1];
    const float* ln_msa_g  = (const float*)d_in[2];
    const float* ln_msa_b  = (const float*)d_in[3];
    const float* ln_pair_g = (const float*)d_in[4];
    const float* ln_pair_b = (const float*)d_in[5];
    const float* sw_q_w    = (const float*)d_in[6];
    const float* sw_q_b    = (const float*)d_in[7];
    const float* sw_k_w    = (const float*)d_in[8];
    const float* sw_k_b    = (const float*)d_in[9];
    const float* wq        = (const float*)d_in[10];
    const float* wk        = (const float*)d_in[11];
    const float* wv        = (const float*)d_in[12];
    const float* wb        = (const float*)d_in[13];
    const float* wg        = (const float*)d_in[14];
    const float* bg        = (const float*)d_in[15];
    const float* wo        = (const float*)d_in[16];
    const float* bo        = (const float*)d_in[17];
    float* out = (float*)d_out;

    ln_msa_kernel<<<MROWS, 256>>>(msa, ln_msa_g, ln_msa_b);
    pair_bias_kernel<<<PROWS, 128>>>(pair, ln_pair_g, ln_pair_b, wb);
    swq_kernel<<<LRES, 256>>>(sw_q_w, sw_q_b);

    dim3 gp(MROWS/64, 4);
    sgemm256<<<gp, 256>>>(sw_k_w, sw_k_b, nullptr, 0);
    sgemm256<<<gp, 256>>>(wq,     nullptr, nullptr, 1);
    sgemm256<<<gp, 256>>>(wk,     nullptr, nullptr, 2);
    sgemm256<<<gp, 256>>>(wv,     nullptr, nullptr, 3);
    sgemm256<<<gp, 256>>>(wg,     bg,      nullptr, 4);

    seqw_kernel<<<dim3(LRES, NH), 256>>>();
    attn_gemm_kernel<<<dim3(6, 6, NH), 256>>>();
    attn_softmax_kernel<<<dim3(LRES, NH), 128>>>();
    out_gemm_kernel<<<dim3(6, NSEQ, NH), 256>>>();

    sgemm256<<<gp, 256>>>(wo, bo, out, 5);
}

// round 11
// speedup vs baseline: 1.3118x; 1.3118x over previous
#include <cuda_runtime.h>
#include <cuda_bf16.h>
#include <cstdint>
#include <math.h>

// ---------------- problem constants ----------------
#define NSEQ 256
#define LRES 384
#define DM   256
#define DP   128
#define NH   8
#define DH   32
#define MROWS (NSEQ*LRES)       // 98304
#define PROWS (LRES*LRES)       // 147456
#define SCALE 0.17677669529663687f  // 1/sqrt(32)

// ---------------- scratch (static device globals; no allocation) ----------------
__device__ float g_msa_n[LRES*DM];            // only rows n=0 (for swq)
__device__ __nv_bfloat16 g_msa_hi[MROWS*DM];
__device__ __nv_bfloat16 g_msa_lo[MROWS*DM];
__device__ __nv_bfloat16 g_o_hi [MROWS*DM];
__device__ __nv_bfloat16 g_o_lo [MROWS*DM];
__device__ __nv_bfloat16 g_wt_hi[6*DM*DM];    // transposed weights [w][n][k]
__device__ __nv_bfloat16 g_wt_lo[6*DM*DM];
__device__ float g_q    [MROWS*DM];
__device__ float g_k    [MROWS*DM];
__device__ float g_v    [MROWS*DM];
__device__ float g_gate [MROWS*DM];
__device__ float g_swk  [MROWS*DM];
__device__ float g_swq  [LRES*DM];
__device__ float g_bias [NH*PROWS];
__device__ float g_attn [NH*PROWS];

// ---------------- warp-level bf16 MMA (arch-portable HMMA; compiles for compute_103) ----------------
__device__ __forceinline__ void mma16816(float* c, const uint32_t* a, const uint32_t* b) {
    asm volatile(
        "mma.sync.aligned.m16n8k16.row.col.f32.bf16.bf16.f32 "
        "{%0,%1,%2,%3}, {%4,%5,%6,%7}, {%8,%9}, {%0,%1,%2,%3};"
        : "+f"(c[0]), "+f"(c[1]), "+f"(c[2]), "+f"(c[3])
        : "r"(a[0]), "r"(a[1]), "r"(a[2]), "r"(a[3]), "r"(b[0]), "r"(b[1]));
}

// ---------------- 1) LayerNorm over msa -> hi/lo bf16 (+ f32 rows n=0) ----------------
__global__ __launch_bounds__(256) void ln_msa_kernel(
    const float* __restrict__ msa, const float* __restrict__ g, const float* __restrict__ b)
{
    int row = blockIdx.x;
    int t   = threadIdx.x;
    float x = msa[(size_t)row*DM + t];
    float s = x, s2 = x*x;
    #pragma unroll
    for (int o = 16; o > 0; o >>= 1) {
        s  += __shfl_xor_sync(0xffffffffu, s,  o);
        s2 += __shfl_xor_sync(0xffffffffu, s2, o);
    }
    __shared__ float ws[8], ws2[8];
    int w = t >> 5;
    if ((t & 31) == 0) { ws[w] = s; ws2[w] = s2; }
    __syncthreads();
    float tot = 0.f, tot2 = 0.f;
    #pragma unroll
    for (int i = 0; i < 8; i++) { tot += ws[i]; tot2 += ws2[i]; }
    float mean = tot * (1.0f/DM);
    float var  = tot2 * (1.0f/DM) - mean*mean;
    float rs   = rsqrtf(var + 1e-5f);
    float y = (x - mean) * rs * g[t] + b[t];
    __nv_bfloat16 h = __float2bfloat16(y);
    g_msa_hi[(size_t)row*DM + t] = h;
    g_msa_lo[(size_t)row*DM + t] = __float2bfloat16(y - __bfloat162float(h));
    if (row < LRES) g_msa_n[row*DM + t] = y;
}

// ---------------- 2) pair LayerNorm fused with bias = pair_n @ wb ----------------
__global__ __launch_bounds__(128) void pair_bias_kernel(
    const float* __restrict__ pair, const float* __restrict__ g, const float* __restrict__ b,
    const float* __restrict__ wb)
{
    int r = blockIdx.x;
    int t = threadIdx.x;
    float x = pair[(size_t)r*DP + t];
    float s = x, s2 = x*x;
    #pragma unroll
    for (int o = 16; o > 0; o >>= 1) {
        s  += __shfl_xor_sync(0xffffffffu, s,  o);
        s2 += __shfl_xor_sync(0xffffffffu, s2, o);
    }
    __shared__ float ws[4], ws2[4];
    int w = t >> 5;
    if ((t & 31) == 0) { ws[w] = s; ws2[w] = s2; }
    __syncthreads();
    float tot = ws[0]+ws[1]+ws[2]+ws[3];
    float tot2 = ws2[0]+ws2[1]+ws2[2]+ws2[3];
    float mean = tot * (1.0f/DP);
    float var  = tot2 * (1.0f/DP) - mean*mean;
    float rs   = rsqrtf(var + 1e-5f);
    float xn   = (x - mean) * rs * g[t] + b[t];

    float acc[NH];
    #pragma unroll
    for (int h = 0; h < NH; h++) acc[h] = xn * wb[t*NH + h];
    #pragma unroll
    for (int o = 16; o > 0; o >>= 1) {
        #pragma unroll
        for (int h = 0; h < NH; h++) acc[h] += __shfl_xor_sync(0xffffffffu, acc[h], o);
    }
    __shared__ float part[4][NH];
    if ((t & 31) == 0) {
        #pragma unroll
        for (int h = 0; h < NH; h++) part[w][h] = acc[h];
    }
    __syncthreads();
    if (t < NH) {
        float v = part[0][t] + part[1][t] + part[2][t] + part[3][t];
        g_bias[(size_t)t*PROWS + r] = v;
    }
}

// ---------------- 3) transpose + split weights: g_wt[w][n][k] = split(W_w[k][n]) ----------------
__global__ __launch_bounds__(256) void wt_prep_kernel(
    const float* __restrict__ w0, const float* __restrict__ w1, const float* __restrict__ w2,
    const float* __restrict__ w3, const float* __restrict__ w4, const float* __restrict__ w5)
{
    int k = blockIdx.x;
    int widx = blockIdx.y;
    int n = threadIdx.x;
    const float* W = (widx==0)?w0:(widx==1)?w1:(widx==2)?w2:(widx==3)?w3:(widx==4)?w4:w5;
    float x = W[k*DM + n];
    __nv_bfloat16 h = __float2bfloat16(x);
    size_t idx = ((size_t)widx*DM + n)*DM + k;
    g_wt_hi[idx] = h;
    g_wt_lo[idx] = __float2bfloat16(x - __bfloat162float(h));
}

// ---------------- 4) swq = (tar @ sw_q_w + b) * scale ----------------
__global__ __launch_bounds__(256) void swq_kernel(
    const float* __restrict__ sw_q_w, const float* __restrict__ sw_q_b)
{
    int l = blockIdx.x;
    int j = threadIdx.x;
    __shared__ float tarr[DM];
    tarr[j] = g_msa_n[l*DM + j];
    __syncthreads();
    float acc = sw_q_b[j];
    #pragma unroll 8
    for (int d = 0; d < DM; d++) acc += tarr[d] * sw_q_w[d*DM + j];
    g_swq[l*DM + j] = acc * SCALE;
}

// ---------------- 5) bf16 hi/lo MMA GEMM: C[m,n] = sum_k A[m,k] * W_w[k,n] ----------------
// block tile 128x64, KC=32, 8 warps (4x2), warp tile 32x32
// epilogue per w: 0 +swk_b | 1 none | 2 *SCALE | 3 none | 4 sigmoid(+bias) | 5 +bias -> outx
#define BM 128
#define BN 64
#define KC 32
#define KSTR (KC + 8)   // bf16 stride: 40 elems = 80 B (16B-aligned rows)

__global__ __launch_bounds__(256) void bf16_gemm(
    const __nv_bfloat16* __restrict__ Ahi, const __nv_bfloat16* __restrict__ Alo,
    int w, const float* __restrict__ bias, float* __restrict__ outx)
{
    __shared__ __nv_bfloat16 sA[2][BM][KSTR];
    __shared__ __nv_bfloat16 sB[2][BN][KSTR];

    int m0 = blockIdx.x * BM, n0 = blockIdx.y * BN;
    int tid = threadIdx.x;
    int warp = tid >> 5, lane = tid & 31;
    int wm = warp >> 1, wn = warp & 1;          // warp grid 4 (M) x 2 (N)
    int lr = lane >> 2, lc = lane & 3;          // fragment row/col within 8x8

    const __nv_bfloat16* Bhi = &g_wt_hi[((size_t)w*DM + n0)*DM];
    const __nv_bfloat16* Blo = &g_wt_lo[((size_t)w*DM + n0)*DM];

    float c[2][4][4];
    #pragma unroll
    for (int i = 0; i < 2; i++)
        #pragma unroll
        for (int j = 0; j < 4; j++)
            #pragma unroll
            for (int e = 0; e < 4; e++) c[i][j][e] = 0.f;

    int ar = tid >> 1, ah = (tid & 1) * 16;     // A loader: row, k-half
    int br = tid >> 2, bs = (tid & 3) * 8;      // B loader: row, k-seg

    for (int kc = 0; kc < DM; kc += KC) {
        // stage A (128x32 hi+lo) and B (64x32 hi+lo)
        {
            const uint4* ghi = (const uint4*)&Ahi[(size_t)(m0 + ar)*DM + kc + ah];
            const uint4* glo = (const uint4*)&Alo[(size_t)(m0 + ar)*DM + kc + ah];
            uint4 h0 = ghi[0], h1 = ghi[1], l0 = glo[0], l1 = glo[1];
            *(uint4*)&sA[0][ar][ah]     = h0;
            *(uint4*)&sA[0][ar][ah + 8] = h1;
            *(uint4*)&sA[1][ar][ah]     = l0;
            *(uint4*)&sA[1][ar][ah + 8] = l1;
            uint4 bh = *(const uint4*)&Bhi[(size_t)br*DM + kc + bs];
            uint4 bl = *(const uint4*)&Blo[(size_t)br*DM + kc + bs];
            *(uint4*)&sB[0][br][bs] = bh;
            *(uint4*)&sB[1][br][bs] = bl;
        }
        __syncthreads();

        #pragma unroll
        for (int ks = 0; ks < 2; ks++) {
            int k0 = ks * 16;
            uint32_t afh[2][4], afl[2][4], bfh[4][2], bfl[4][2];
            #pragma unroll
            for (int mt = 0; mt < 2; mt++) {
                int r = wm*32 + mt*16 + lr;
                int cc = k0 + lc*2;
                afh[mt][0] = *(const uint32_t*)&sA[0][r    ][cc    ];
                afh[mt][1] = *(const uint32_t*)&sA[0][r + 8][cc    ];
                afh[mt][2] = *(const uint32_t*)&sA[0][r    ][cc + 8];
                afh[mt][3] = *(const uint32_t*)&sA[0][r + 8][cc + 8];
                afl[mt][0] = *(const uint32_t*)&sA[1][r    ][cc    ];
                afl[mt][1] = *(const uint32_t*)&sA[1][r + 8][cc    ];
                afl[mt][2] = *(const uint32_t*)&sA[1][r    ][cc + 8];
                afl[mt][3] = *(const uint32_t*)&sA[1][r + 8][cc + 8];
            }
            #pragma unroll
            for (int nt = 0; nt < 4; nt++) {
                int n = wn*32 + nt*8 + lr;
                int kk = k0 + lc*2;
                bfh[nt][0] = *(const uint32_t*)&sB[0][n][kk    ];
                bfh[nt][1] = *(const uint32_t*)&sB[0][n][kk + 8];
                bfl[nt][0] = *(const uint32_t*)&sB[1][n][kk    ];
                bfl[nt][1] = *(const uint32_t*)&sB[1][n][kk + 8];
            }
            #pragma unroll
            for (int mt = 0; mt < 2; mt++)
                #pragma unroll
                for (int nt = 0; nt < 4; nt++) {
                    mma16816(c[mt][nt], afh[mt], bfh[nt]);
                    mma16816(c[mt][nt], afh[mt], bfl[nt]);
                    mma16816(c[mt][nt], afl[mt], bfh[nt]);
                }
        }
        __syncthreads();
    }

    // epilogue
    float* C = (w==0) ? g_swk : (w==1) ? g_q : (w==2) ? g_k :
               (w==3) ? g_v  : (w==4) ? g_gate : outx;
    #pragma unroll
    for (int mt = 0; mt < 2; mt++) {
        #pragma unroll
        for (int nt = 0; nt < 4; nt++) {
            #pragma unroll
            for (int half = 0; half < 2; half++) {
                int row = m0 + wm*32 + mt*16 + lr + half*8;
                int col = n0 + wn*32 + nt*8 + lc*2;
                float x0 = c[mt][nt][half*2 + 0];
                float x1 = c[mt][nt][half*2 + 1];
                if (w == 0) {
                    x0 += bias[col]; x1 += bias[col + 1];
                } else if (w == 2) {
                    x0 *= SCALE; x1 *= SCALE;
                } else if (w == 4) {
                    x0 = 1.f/(1.f + __expf(-(x0 + bias[col])));
                    x1 = 1.f/(1.f + __expf(-(x1 + bias[col + 1])));
                } else if (w == 5) {
                    x0 += bias[col]; x1 += bias[col + 1];
                }
                float2 v; v.x = x0; v.y = x1;
                *(float2*)&C[(size_t)row*DM + col] = v;
            }
        }
    }
}

// ---------------- 6) seq-weight: softmax over n, scale q in place ----------------
__global__ __launch_bounds__(256) void seqw_kernel()
{
    int l = blockIdx.x, h = blockIdx.y;
    int n = threadIdx.x;
    __shared__ float qv[DH];
    __shared__ float red[8];
    if (n < DH) qv[n] = g_swq[l*DM + h*DH + n];
    __syncthreads();

    const float* kp = &g_swk[((size_t)n*LRES + l)*DM + h*DH];
    float dot = 0.f;
    #pragma unroll
    for (int d = 0; d < DH; d += 4) {
        float4 kv = *(const float4*)&kp[d];
        dot += qv[d]*kv.x + qv[d+1]*kv.y + qv[d+2]*kv.z + qv[d+3]*kv.w;
    }
    float m = dot;
    #pragma unroll
    for (int o = 16; o > 0; o >>= 1) m = fmaxf(m, __shfl_xor_sync(0xffffffffu, m, o));
    int w = n >> 5;
    if ((n & 31) == 0) red[w] = m;
    __syncthreads();
    float mx = red[0];
    #pragma unroll
    for (int i = 1; i < 8; i++) mx = fmaxf(mx, red[i]);
    __syncthreads();
    float e = __expf(dot - mx);
    float s = e;
    #pragma unroll
    for (int o = 16; o > 0; o >>= 1) s += __shfl_xor_sync(0xffffffffu, s, o);
    if ((n & 31) == 0) red[w] = s;
    __syncthreads();
    float tot = 0.f;
    #pragma unroll
    for (int i = 0; i < 8; i++) tot += red[i];
    float wgt = e / tot;

    float* qp = &g_q[((size_t)n*LRES + l)*DM + h*DH];
    #pragma unroll
    for (int d = 0; d < DH; d += 4) {
        float4 v = *(float4*)&qp[d];
        v.x *= wgt; v.y *= wgt; v.z *= wgt; v.w *= wgt;
        *(float4*)&qp[d] = v;
    }
}

// ---------------- 7) attn logits ----------------
__global__ __launch_bounds__(256) void attn_gemm_kernel()
{
    int h  = blockIdx.z;
    int q0 = blockIdx.x * 64, k0 = blockIdx.y * 64;
    __shared__ float Qs[64][33];
    __shared__ float Ks[64][33];
    int tid = threadIdx.x;
    int tx = tid & 15, ty = tid >> 4;
    float acc[4][4] = {};

    for (int s = 0; s < NSEQ; s++) {
        #pragma unroll
        for (int i = 0; i < 2; i++) {
            int id = tid + i*256;
            int r = id >> 3, c4 = (id & 7) * 4;
            float4 v = *(const float4*)&g_q[((size_t)s*LRES + q0 + r)*DM + h*DH + c4];
            Qs[r][c4+0] = v.x; Qs[r][c4+1] = v.y; Qs[r][c4+2] = v.z; Qs[r][c4+3] = v.w;
            float4 u = *(const float4*)&g_k[((size_t)s*LRES + k0 + r)*DM + h*DH + c4];
            Ks[r][c4+0] = u.x; Ks[r][c4+1] = u.y; Ks[r][c4+2] = u.z; Ks[r][c4+3] = u.w;
        }
        __syncthreads();
        #pragma unroll
        for (int d = 0; d < 32; d++) {
            float a0 = Qs[ty*4+0][d], a1 = Qs[ty*4+1][d], a2 = Qs[ty*4+2][d], a3 = Qs[ty*4+3][d];
            float b0 = Ks[tx*4+0][d], b1 = Ks[tx*4+1][d], b2 = Ks[tx*4+2][d], b3 = Ks[tx*4+3][d];
            acc[0][0] += a0*b0; acc[0][1] += a0*b1; acc[0][2] += a0*b2; acc[0][3] += a0*b3;
            acc[1][0] += a1*b0; acc[1][1] += a1*b1; acc[1][2] += a1*b2; acc[1][3] += a1*b3;
            acc[2][0] += a2*b0; acc[2][1] += a2*b1; acc[2][2] += a2*b2; acc[2][3] += a2*b3;
            acc[3][0] += a3*b0; acc[3][1] += a3*b1; acc[3][2] += a3*b2; acc[3][3] += a3*b3;
        }
        __syncthreads();
    }
    #pragma unroll
    for (int i = 0; i < 4; i++)
        #pragma unroll
        for (int j = 0; j < 4; j++)
            g_attn[(size_t)h*PROWS + (q0 + ty*4 + i)*LRES + (k0 + tx*4 + j)] = acc[i][j];
}

// ---------------- 8) softmax over k of (logits + bias) ----------------
__global__ __launch_bounds__(128) void attn_softmax_kernel()
{
    int q = blockIdx.x, h = blockIdx.y;
    int t = threadIdx.x;
    size_t base = (size_t)h*PROWS + (size_t)q*LRES;
    float v0 = g_attn[base + t      ] + g_bias[base + t      ];
    float v1 = g_attn[base + t + 128] + g_bias[base + t + 128];
    float v2 = g_attn[base + t + 256] + g_bias[base + t + 256];
    float m = fmaxf(v0, fmaxf(v1, v2));
    #pragma unroll
    for (int o = 16; o > 0; o >>= 1) m = fmaxf(m, __shfl_xor_sync(0xffffffffu, m, o));
    __shared__ float red[4];
    int w = t >> 5;
    if ((t & 31) == 0) red[w] = m;
    __syncthreads();
    float mx = fmaxf(fmaxf(red[0], red[1]), fmaxf(red[2], red[3]));
    __syncthreads();
    float e0 = __expf(v0 - mx), e1 = __expf(v1 - mx), e2 = __expf(v2 - mx);
    float s = e0 + e1 + e2;
    #pragma unroll
    for (int o = 16; o > 0; o >>= 1) s += __shfl_xor_sync(0xffffffffu, s, o);
    if ((t & 31) == 0) red[w] = s;
    __syncthreads();
    float tot = red[0] + red[1] + red[2] + red[3];
    float inv = 1.f / tot;
    g_attn[base + t      ] = e0 * inv;
    g_attn[base + t + 128] = e1 * inv;
    g_attn[base + t + 256] = e2 * inv;
}

// ---------------- 9) out = attn @ v, gated; emit bf16 hi/lo for final GEMM ----------------
__global__ __launch_bounds__(256) void out_gemm_kernel()
{
    int q0 = blockIdx.x * 64;
    int s  = blockIdx.y;
    int h  = blockIdx.z;
    __shared__ float As[64][33];
    __shared__ float Bs[32][33];
    int tid = threadIdx.x;
    int tx = tid & 15, ty = tid >> 4;
    float acc[4][2] = {};

    for (int k0 = 0; k0 < LRES; k0 += 32) {
        #pragma unroll
        for (int i = 0; i < 2; i++) {
            int id = tid + i*256;
            int r = id >> 3, c4 = (id & 7) * 4;
            float4 v = *(const float4*)&g_attn[(size_t)h*PROWS + (q0 + r)*LRES + k0 + c4];
            As[r][c4+0] = v.x; As[r][c4+1] = v.y; As[r][c4+2] = v.z; As[r][c4+3] = v.w;
        }
        {
            int r = tid >> 3, c4 = (tid & 7) * 4;
            float4 v = *(const float4*)&g_v[((size_t)s*LRES + k0 + r)*DM + h*DH + c4];
            Bs[r][c4+0] = v.x; Bs[r][c4+1] = v.y; Bs[r][c4+2] = v.z; Bs[r][c4+3] = v.w;
        }
        __syncthreads();
        #pragma unroll
        for (int kk = 0; kk < 32; kk++) {
            float b0 = Bs[kk][tx*2], b1 = Bs[kk][tx*2+1];
            #pragma unroll
            for (int i = 0; i < 4; i++) {
                float a = As[ty*4+i][kk];
                acc[i][0] += a * b0;
                acc[i][1] += a * b1;
            }
        }
        __syncthreads();
    }
    #pragma unroll
    for (int i = 0; i < 4; i++) {
        int q = q0 + ty*4 + i;
        size_t idx = ((size_t)s*LRES + q)*DM + h*DH + tx*2;
        float o0 = acc[i][0] * g_gate[idx  ];
        float o1 = acc[i][1] * g_gate[idx+1];
        __nv_bfloat16 h0 = __float2bfloat16(o0);
        __nv_bfloat16 h1 = __float2bfloat16(o1);
        g_o_hi[idx  ] = h0; g_o_lo[idx  ] = __float2bfloat16(o0 - __bfloat162float(h0));
        g_o_hi[idx+1] = h1; g_o_lo[idx+1] = __float2bfloat16(o1 - __bfloat162float(h1));
    }
}

// ---------------- launch ----------------
extern "C" void kernel_launch(void* const* d_in, const int* in_sizes, int n_in,
                              void* d_out, int out_size)
{
    (void)in_sizes; (void)n_in; (void)out_size;
    const float* msa       = (const float*)d_in[0];
    const float* pair      = (const float*)d_in[1];
    const float* ln_msa_g  = (const float*)d_in[2];
    const float* ln_msa_b  = (const float*)d_in[3];
    const float* ln_pair_g = (const float*)d_in[4];
    const float* ln_pair_b = (const float*)d_in[5];
    const float* sw_q_w    = (const float*)d_in[6];
    const float* sw_q_b    = (const float*)d_in[7];
    const float* sw_k_w    = (const float*)d_in[8];
    const float* sw_k_b    = (const float*)d_in[9];
    const float* wq        = (const float*)d_in[10];
    const float* wk        = (const float*)d_in[11];
    const float* wv        = (const float*)d_in[12];
    const float* wb        = (const float*)d_in[13];
    const float* wg        = (const float*)d_in[14];
    const float* bg        = (const float*)d_in[15];
    const float* wo        = (const float*)d_in[16];
    const float* bo        = (const float*)d_in[17];
    float* out = (float*)d_out;

    ln_msa_kernel<<<MROWS, 256>>>(msa, ln_msa_g, ln_msa_b);
    pair_bias_kernel<<<PROWS, 128>>>(pair, ln_pair_g, ln_pair_b, wb);
    wt_prep_kernel<<<dim3(DM, 6), 256>>>(sw_k_w, wq, wk, wv, wg, wo);
    swq_kernel<<<LRES, 256>>>(sw_q_w, sw_q_b);

    // device-global bf16 operand pointers (resolve via symbol addresses on device side):
    // bf16_gemm reads A from the passed pointers; pass the device-global arrays directly.
    // (Taking the address of a __device__ array in host code yields the device address
    //  under nvcc whole-program compilation; these are compile-time device symbols.)
    __nv_bfloat16* msa_hi_p; __nv_bfloat16* msa_lo_p;
    __nv_bfloat16* o_hi_p;   __nv_bfloat16* o_lo_p;
    cudaGetSymbolAddress((void**)&msa_hi_p, g_msa_hi);
    cudaGetSymbolAddress((void**)&msa_lo_p, g_msa_lo);
    cudaGetSymbolAddress((void**)&o_hi_p,   g_o_hi);
    cudaGetSymbolAddress((void**)&o_lo_p,   g_o_lo);

    dim3 gg(MROWS/BM, DM/BN);   // (768, 4)
    bf16_gemm<<<gg, 256>>>(msa_hi_p, msa_lo_p, 0, sw_k_b, nullptr);
    bf16_gemm<<<gg, 256>>>(msa_hi_p, msa_lo_p, 1, nullptr, nullptr);
    bf16_gemm<<<gg, 256>>>(msa_hi_p, msa_lo_p, 2, nullptr, nullptr);
    bf16_gemm<<<gg, 256>>>(msa_hi_p, msa_lo_p, 3, nullptr, nullptr);
    bf16_gemm<<<gg, 256>>>(msa_hi_p, msa_lo_p, 4, bg, nullptr);

    seqw_kernel<<<dim3(LRES, NH), 256>>>();
    attn_gemm_kernel<<<dim3(6, 6, NH), 256>>>();
    attn_softmax_kernel<<<dim3(LRES, NH), 128>>>();
    out_gemm_kernel<<<dim3(6, NSEQ, NH), 256>>>();

    bf16_gemm<<<gg, 256>>>(o_hi_p, o_lo_p, 5, bo, out);
}